// round 6
// baseline (speedup 1.0000x reference)
#include <cuda_runtime.h>
#include <cuda_fp16.h>
#include <cuda_bf16.h>
#include <cstddef>

// Problem constants
#define B_   4
#define D_   256
#define E_   512
#define C_   256
#define NEG_INF -1e9f

// Scratch (no cudaMalloc allowed)
__device__ __half g_enc_proj[B_ * E_ * C_];   // [b, e, o] half
__device__ __half g_dec_proj[B_ * D_ * C_];   // [b, d, o] half
__device__ float  g_scores[B_ * D_ * E_];     // [b, d, e]

__device__ __forceinline__ __half2 tanh2h(__half2 x) {
    unsigned int r, xi = *reinterpret_cast<unsigned int*>(&x);
    asm("tanh.approx.f16x2 %0, %1;" : "=r"(r) : "r"(xi));
    return *reinterpret_cast<__half2*>(&r);
}
__device__ __forceinline__ __half2 u2h(unsigned int u) {
    return *reinterpret_cast<__half2*>(&u);
}

// ---------------------------------------------------------------------------
// Fused GEMM: out[b,r,o] = sum_c X[b,r,c] * W[o,c], output stored as half.
// Tile 64 rows x 32 cols, BK=16, 128 threads, 4x4 micro-tile.
// Double-buffered smem: one __syncthreads per k-iter, compute overlaps LDG.
// grid: x = 8 col tiles, y = 12 row tiles (0..7 enc R=512, 8..11 dec R=256), z = B.
// ---------------------------------------------------------------------------
__global__ __launch_bounds__(128) void gemm_fused_kernel(
        const float* __restrict__ enc, const float* __restrict__ dec,
        const float* __restrict__ W1,  const float* __restrict__ W2) {
    __shared__ float Xs[2][16][68];
    __shared__ float Ws[2][16][36];

    const int b  = blockIdx.z;
    const int yt = blockIdx.y;
    const bool is_enc = (yt < 8);
    const int R      = is_enc ? E_ : D_;
    const int row0   = (is_enc ? yt : yt - 8) * 64;
    const int col0   = blockIdx.x * 32;
    const float* X   = is_enc ? enc : dec;
    const float* W   = is_enc ? W1  : W2;
    __half* out      = is_enc ? g_enc_proj : g_dec_proj;

    const int t  = threadIdx.x;
    const int lr = t >> 2;           // 0..31
    const int lc = (t & 3) << 2;     // 0,4,8,12
    const int ty = t >> 3;           // 0..15 (row group)
    const int tx = t & 7;            // 0..7  (col group)

    const float* Xb = X + ((size_t)b * R + row0 + lr) * C_ + lc;
    const float* Wb = W + (size_t)(col0 + lr) * C_ + lc;

    float4 xa0 = *(const float4*)Xb;
    float4 xa1 = *(const float4*)(Xb + 32 * C_);
    float4 wa  = *(const float4*)Wb;

    float acc[4][4];
#pragma unroll
    for (int i = 0; i < 4; i++)
#pragma unroll
        for (int j = 0; j < 4; j++) acc[i][j] = 0.f;

    // stage k0 = 0 into buffer 0
    Xs[0][lc + 0][lr] = xa0.x; Xs[0][lc + 1][lr] = xa0.y;
    Xs[0][lc + 2][lr] = xa0.z; Xs[0][lc + 3][lr] = xa0.w;
    Xs[0][lc + 0][lr + 32] = xa1.x; Xs[0][lc + 1][lr + 32] = xa1.y;
    Xs[0][lc + 2][lr + 32] = xa1.z; Xs[0][lc + 3][lr + 32] = xa1.w;
    Ws[0][lc + 0][lr] = wa.x; Ws[0][lc + 1][lr] = wa.y;
    Ws[0][lc + 2][lr] = wa.z; Ws[0][lc + 3][lr] = wa.w;
    __syncthreads();

    int p = 0;
    for (int k0 = 0; k0 < C_; k0 += 16) {
        const bool next = (k0 + 16 < C_);
        if (next) {
            xa0 = *(const float4*)(Xb + k0 + 16);
            xa1 = *(const float4*)(Xb + 32 * C_ + k0 + 16);
            wa  = *(const float4*)(Wb + k0 + 16);
        }
#pragma unroll
        for (int kk = 0; kk < 16; kk++) {
            float4 a4 = *(const float4*)&Xs[p][kk][ty * 4];
            float4 b4 = *(const float4*)&Ws[p][kk][tx * 4];
            float a[4] = {a4.x, a4.y, a4.z, a4.w};
            float bb[4] = {b4.x, b4.y, b4.z, b4.w};
#pragma unroll
            for (int i = 0; i < 4; i++)
#pragma unroll
                for (int j = 0; j < 4; j++)
                    acc[i][j] = fmaf(a[i], bb[j], acc[i][j]);
        }
        if (next) {
            const int q = p ^ 1;
            Xs[q][lc + 0][lr] = xa0.x; Xs[q][lc + 1][lr] = xa0.y;
            Xs[q][lc + 2][lr] = xa0.z; Xs[q][lc + 3][lr] = xa0.w;
            Xs[q][lc + 0][lr + 32] = xa1.x; Xs[q][lc + 1][lr + 32] = xa1.y;
            Xs[q][lc + 2][lr + 32] = xa1.z; Xs[q][lc + 3][lr + 32] = xa1.w;
            Ws[q][lc + 0][lr] = wa.x; Ws[q][lc + 1][lr] = wa.y;
            Ws[q][lc + 2][lr] = wa.z; Ws[q][lc + 3][lr] = wa.w;
        }
        __syncthreads();
        p ^= 1;
    }

#pragma unroll
    for (int i = 0; i < 4; i++) {
        __half2 h0 = __floats2half2_rn(acc[i][0], acc[i][1]);
        __half2 h1 = __floats2half2_rn(acc[i][2], acc[i][3]);
        uint2 pk = make_uint2(*reinterpret_cast<unsigned int*>(&h0),
                              *reinterpret_cast<unsigned int*>(&h1));
        *(uint2*)(out + ((size_t)b * R + row0 + ty * 4 + i) * C_ + col0 + tx * 4) = pk;
    }
}

// ---------------------------------------------------------------------------
// Scores v2: s[b,d,e] = sum_c tanh(dec_proj[b,d,c] + enc_proj[b,e,c]) * v[c]
// CTA tile: 32 d x 64 e, 256 threads. Thread (dg = t>>5 in 0..7, el = t&31)
// computes 4 d's (dg*4..+3) x 2 e's (el, el+32) = 8 accumulators.
// Per 8-c chunk: 7 LDS.128 for 64 elements (~1.3 B/elem); dp loads are
// warp-broadcast (all lanes same dg). ep pitch 132 uints -> conflict-free
// LDS.128 (8-lane phases cover all 32 banks). Flush h2 accs to fp32 / 32 c.
// ---------------------------------------------------------------------------
#define ETILE 64
#define DTILE 32
#define PITCH 132
#define SCORES_SMEM ((ETILE * PITCH + DTILE * PITCH + 128) * 4)

__global__ __launch_bounds__(256) void scores_kernel(const float* __restrict__ v_g) {
    extern __shared__ unsigned int smu[];
    unsigned int* ep  = smu;                        // ETILE rows of PITCH half2
    unsigned int* dpu = ep + ETILE * PITCH;         // DTILE rows of PITCH half2
    unsigned int* vsu = dpu + DTILE * PITCH;        // 128 half2

    const int b  = blockIdx.z;
    const int d0 = blockIdx.y * DTILE;
    const int e0 = blockIdx.x * ETILE;
    const int t  = threadIdx.x;

    // Fill ep: 64 rows, each row = 256 halves = 32 uint4
    const __half* encb = g_enc_proj + ((size_t)b * E_ + e0) * C_;
    for (int i = t; i < ETILE * 32; i += 256) {
        int r = i >> 5, q = i & 31;
        uint4 s = ((const uint4*)encb)[r * 32 + q];
        *(uint4*)(ep + r * PITCH + q * 4) = s;
    }
    // Fill dp: 32 rows x 32 uint4
    const __half* decb = g_dec_proj + ((size_t)b * D_ + d0) * C_;
    for (int i = t; i < DTILE * 32; i += 256) {
        int r = i >> 5, q = i & 31;
        uint4 s = ((const uint4*)decb)[r * 32 + q];
        *(uint4*)(dpu + r * PITCH + q * 4) = s;
    }
    // Fill v as half2
    if (t < 128) {
        float2 vf = ((const float2*)v_g)[t];
        __half2 vh = __floats2half2_rn(vf.x, vf.y);
        vsu[t] = *reinterpret_cast<unsigned int*>(&vh);
    }
    __syncthreads();

    const int el = t & 31;
    const int dg = t >> 5;
    const unsigned int* ep0 = ep + el * PITCH;
    const unsigned int* ep1 = ep + (el + 32) * PITCH;
    const unsigned int* dpr = dpu + (dg * 4) * PITCH;

    __half2 a2[8];
    float facc[8];
#pragma unroll
    for (int i = 0; i < 8; i++) { a2[i] = __floats2half2_rn(0.f, 0.f); facc[i] = 0.f; }

    for (int c8 = 0; c8 < 128; c8 += 4) {       // 4 half2 = 8 c per chunk
        uint4 eu0 = *(const uint4*)(ep0 + c8);
        uint4 eu1 = *(const uint4*)(ep1 + c8);
        uint4 vu  = *(const uint4*)(vsu + c8);
        __half2 v0 = u2h(vu.x), v1 = u2h(vu.y), v2 = u2h(vu.z), v3 = u2h(vu.w);
#pragma unroll
        for (int i = 0; i < 4; i++) {
            uint4 du = *(const uint4*)(dpr + i * PITCH + c8);
            __half2 dh0 = u2h(du.x), dh1 = u2h(du.y), dh2 = u2h(du.z), dh3 = u2h(du.w);
            __half2 s;
            s = a2[i * 2];
            s = __hfma2(tanh2h(__hadd2(dh0, u2h(eu0.x))), v0, s);
            s = __hfma2(tanh2h(__hadd2(dh1, u2h(eu0.y))), v1, s);
            s = __hfma2(tanh2h(__hadd2(dh2, u2h(eu0.z))), v2, s);
            s = __hfma2(tanh2h(__hadd2(dh3, u2h(eu0.w))), v3, s);
            a2[i * 2] = s;
            s = a2[i * 2 + 1];
            s = __hfma2(tanh2h(__hadd2(dh0, u2h(eu1.x))), v0, s);
            s = __hfma2(tanh2h(__hadd2(dh1, u2h(eu1.y))), v1, s);
            s = __hfma2(tanh2h(__hadd2(dh2, u2h(eu1.z))), v2, s);
            s = __hfma2(tanh2h(__hadd2(dh3, u2h(eu1.w))), v3, s);
            a2[i * 2 + 1] = s;
        }
        if ((c8 & 12) == 12) {                  // flush every 32 c's
#pragma unroll
            for (int i = 0; i < 8; i++) {
                float2 f = __half22float2(a2[i]);
                facc[i] += f.x + f.y;
                a2[i] = __floats2half2_rn(0.f, 0.f);
            }
        }
    }

#pragma unroll
    for (int i = 0; i < 4; i++) {
        float* srow = g_scores + ((size_t)b * D_ + d0 + dg * 4 + i) * E_ + e0 + el;
        srow[0]  = facc[i * 2];
        srow[32] = facc[i * 2 + 1];
    }
}

// ---------------------------------------------------------------------------
// Masked log-softmax over E=512 per (b,d) row. One warp per row, 16 elems per
// lane, all reductions in-warp. 8 rows per 256-thread CTA, 128 CTAs.
// mask is bool promoted to int32 (nonzero = keep).
// ---------------------------------------------------------------------------
__global__ __launch_bounds__(256) void softmax_kernel(const int* __restrict__ mask,
                                                      float* __restrict__ out) {
    const int row  = blockIdx.x * 8 + (threadIdx.x >> 5);
    const int lane = threadIdx.x & 31;

    const float4* s = (const float4*)(g_scores + (size_t)row * E_);
    const int4*   m = (const int4*)(mask + (size_t)row * E_);

    float x[16];
    float vmax = -3.0e38f;
#pragma unroll
    for (int q = 0; q < 4; q++) {
        float4 sv = s[q * 32 + lane];
        int4   mv = m[q * 32 + lane];
        x[4 * q + 0] = mv.x ? sv.x : NEG_INF;
        x[4 * q + 1] = mv.y ? sv.y : NEG_INF;
        x[4 * q + 2] = mv.z ? sv.z : NEG_INF;
        x[4 * q + 3] = mv.w ? sv.w : NEG_INF;
        vmax = fmaxf(vmax, fmaxf(fmaxf(x[4 * q], x[4 * q + 1]),
                                 fmaxf(x[4 * q + 2], x[4 * q + 3])));
    }
#pragma unroll
    for (int o = 16; o; o >>= 1)
        vmax = fmaxf(vmax, __shfl_xor_sync(0xffffffffu, vmax, o));

    float sum = 0.f;
#pragma unroll
    for (int k = 0; k < 16; k++) sum += __expf(x[k] - vmax);
#pragma unroll
    for (int o = 16; o; o >>= 1)
        sum += __shfl_xor_sync(0xffffffffu, sum, o);

    const float lse = vmax + logf(sum);

    float* orow = out + (size_t)row * E_;
#pragma unroll
    for (int q = 0; q < 4; q++) {
        float4 o4 = make_float4(x[4 * q] - lse, x[4 * q + 1] - lse,
                                x[4 * q + 2] - lse, x[4 * q + 3] - lse);
        ((float4*)orow)[q * 32 + lane] = o4;
    }
}

// ---------------------------------------------------------------------------
extern "C" void kernel_launch(void* const* d_in, const int* in_sizes, int n_in,
                              void* d_out, int out_size) {
    const float* decoder = (const float*)d_in[0];
    const float* encoder = (const float*)d_in[1];
    const int*   mask    = (const int*)d_in[2];
    const float* W1      = (const float*)d_in[3];
    const float* W2      = (const float*)d_in[4];
    const float* v       = (const float*)d_in[5];
    float* out           = (float*)d_out;

    cudaFuncSetAttribute(scores_kernel,
                         cudaFuncAttributeMaxDynamicSharedMemorySize, SCORES_SMEM);

    // Both projections: y tiles [0,8) -> enc (R=512), [8,12) -> dec (R=256)
    gemm_fused_kernel<<<dim3(8, 12, B_), 128>>>(encoder, decoder, W1, W2);
    // scores (4d x 2e register blocking, h2 SIMD)
    scores_kernel<<<dim3(E_ / ETILE, D_ / DTILE, B_), 256, SCORES_SMEM>>>(v);
    // masked log-softmax, warp per row
    softmax_kernel<<<B_ * D_ / 8, 256>>>(mask, out);
}